// round 1
// baseline (speedup 1.0000x reference)
#include <cuda_runtime.h>

#define N_USER   200000
#define N_ITEM   100000
#define N_NODES_ 300000
#define EMB      80
#define EMBV     20          // float4 chunks per row
#define FEAT     16
#define NNZ_     1000000
#define BATCH_   4096
#define NLAYER   3

// ---------------- device scratch (allowed: __device__ globals) ----------------
static __device__ float g_E [(size_t)N_NODES_ * EMB];   // 96 MB
static __device__ float g_LE[(size_t)N_NODES_ * EMB];   // 96 MB
static __device__ int   g_rowptr[N_NODES_ + 1];
static __device__ int   g_cnt[N_NODES_];                // counts, then scatter cursor
static __device__ int   g_bsum[1024];
static __device__ int   g_winner[N_USER];
static __device__ int   g_cols[NNZ_];
static __device__ float g_vals[NNZ_];

// ---------------- CSR build ----------------
__global__ void k_init() {
    int i = blockIdx.x * blockDim.x + threadIdx.x;
    if (i < N_NODES_) g_cnt[i] = 0;
    if (i < N_USER)   g_winner[i] = -1;
}

__global__ void k_hist(const int* __restrict__ rows) {
    int i = blockIdx.x * blockDim.x + threadIdx.x;
    if (i < NNZ_) atomicAdd(&g_cnt[rows[i]], 1);
}

__global__ void k_scan1() {
    __shared__ int s[1024];
    int tid = threadIdx.x;
    int i = blockIdx.x * 1024 + tid;
    int v = (i < N_NODES_) ? g_cnt[i] : 0;
    s[tid] = v; __syncthreads();
    for (int off = 1; off < 1024; off <<= 1) {
        int t = (tid >= off) ? s[tid - off] : 0;
        __syncthreads();
        s[tid] += t;
        __syncthreads();
    }
    if (i < N_NODES_) g_rowptr[i] = s[tid] - v;       // local exclusive
    if (tid == 1023) g_bsum[blockIdx.x] = s[1023];    // block total
}

__global__ void k_scan2(int nb) {
    __shared__ int s[1024];
    int tid = threadIdx.x;
    int v = (tid < nb) ? g_bsum[tid] : 0;
    s[tid] = v; __syncthreads();
    for (int off = 1; off < 1024; off <<= 1) {
        int t = (tid >= off) ? s[tid - off] : 0;
        __syncthreads();
        s[tid] += t;
        __syncthreads();
    }
    if (tid < nb) g_bsum[tid] = s[tid] - v;           // exclusive block offsets
}

__global__ void k_scan3() {
    int i = blockIdx.x * blockDim.x + threadIdx.x;
    if (i < N_NODES_) {
        int excl = g_rowptr[i] + g_bsum[i >> 10];
        g_rowptr[i] = excl;
        g_cnt[i]    = excl;     // scatter cursor
    }
    if (i == 0) g_rowptr[N_NODES_] = NNZ_;
}

__global__ void k_scatter(const int* __restrict__ rows, const int* __restrict__ cols,
                          const float* __restrict__ vals) {
    int i = blockIdx.x * blockDim.x + threadIdx.x;
    if (i < NNZ_) {
        int p = atomicAdd(&g_cnt[rows[i]], 1);
        g_cols[p] = cols[i];
        g_vals[p] = vals[i];
    }
}

// ---------------- E init + blend scatter ----------------
__global__ void k_init_E(const float4* __restrict__ user_tab, const float4* __restrict__ item_tab) {
    int i = blockIdx.x * blockDim.x + threadIdx.x;   // float4 index
    const int tot_u = N_USER * EMBV;
    const int tot   = N_NODES_ * EMBV;
    if (i < tot_u)      ((float4*)g_E)[i] = user_tab[i];
    else if (i < tot)   ((float4*)g_E)[i] = item_tab[i - tot_u];
}

__global__ void k_winner(const int* __restrict__ u_id) {
    int i = blockIdx.x * blockDim.x + threadIdx.x;
    if (i < BATCH_) atomicMax(&g_winner[u_id[i]], i);
}

__global__ void k_blend(const int* __restrict__ u_id, const int* __restrict__ age,
                        const int* __restrict__ sex, const int* __restrict__ month,
                        const int* __restrict__ day, const int* __restrict__ dow,
                        const float* __restrict__ user_tab,
                        const float* __restrict__ age_tab, const float* __restrict__ sex_tab,
                        const float* __restrict__ month_tab, const float* __restrict__ day_tab,
                        const float* __restrict__ dow_tab) {
    int i = blockIdx.x * blockDim.x + threadIdx.x;
    if (i >= BATCH_) return;
    int u = u_id[i];
    if (g_winner[u] != i) return;   // last occurrence wins (matches sequential scatter-set)
    float*       dst = g_E + (size_t)u * EMB;
    const float* src = user_tab + (size_t)u * EMB;
    const float* t0 = age_tab   + age[i]   * FEAT;
    const float* t1 = sex_tab   + sex[i]   * FEAT;
    const float* t2 = month_tab + month[i] * FEAT;
    const float* t3 = day_tab   + day[i]   * FEAT;
    const float* t4 = dow_tab   + dow[i]   * FEAT;
    #pragma unroll
    for (int j = 0; j < FEAT; j++) {
        dst[0*FEAT+j] = 0.5f * (src[0*FEAT+j] + t0[j]);
        dst[1*FEAT+j] = 0.5f * (src[1*FEAT+j] + t1[j]);
        dst[2*FEAT+j] = 0.5f * (src[2*FEAT+j] + t2[j]);
        dst[3*FEAT+j] = 0.5f * (src[3*FEAT+j] + t3[j]);
        dst[4*FEAT+j] = 0.5f * (src[4*FEAT+j] + t4[j]);
    }
}

// ---------------- SpMM: L_E = Laplacian @ E (warp per row) ----------------
__global__ void k_spmm() {
    int gw   = (blockIdx.x * blockDim.x + threadIdx.x) >> 5;
    int lane = threadIdx.x & 31;
    int nw   = (gridDim.x * blockDim.x) >> 5;
    const float4* E4 = (const float4*)g_E;
    float4*       L4 = (float4*)g_LE;
    for (int row = gw; row < N_NODES_; row += nw) {
        int s = g_rowptr[row], e = g_rowptr[row + 1];
        if (lane < EMBV) {
            float4 acc = make_float4(0.f, 0.f, 0.f, 0.f);
            for (int i = s; i < e; i++) {
                float v = g_vals[i];
                int   c = g_cols[i];
                float4 x = __ldg(&E4[(size_t)c * EMBV + lane]);
                acc.x = fmaf(v, x.x, acc.x);
                acc.y = fmaf(v, x.y, acc.y);
                acc.z = fmaf(v, x.z, acc.z);
                acc.w = fmaf(v, x.w, acc.w);
            }
            L4[(size_t)row * EMBV + lane] = acc;
        }
    }
}

// ---------------- fused GEMM + bias + leaky, in-place E update ----------------
// msg = (L_E+E)@W1 + 2*b1 + (L_E*E)@W2 + b2 ; E = leaky_relu(msg)
#define GBM 64
#define GT  160
#define XS  164   // padded row stride (floats), float4-aligned, conflict-free

__device__ __forceinline__ void fma4(float4& a, float s, const float4 w) {
    a.x = fmaf(s, w.x, a.x);
    a.y = fmaf(s, w.y, a.y);
    a.z = fmaf(s, w.z, a.z);
    a.w = fmaf(s, w.w, a.w);
}

__global__ __launch_bounds__(GT) void k_gemm(const float* __restrict__ W1l,
                                             const float* __restrict__ b1l,
                                             const float* __restrict__ W2l,
                                             const float* __restrict__ b2l) {
    __shared__ float Xs[GBM * XS];   // 41.98 KB: [row][k], k 0..79 = L+E, 80..159 = L*E
    __shared__ float Bs[EMB];

    int tid  = threadIdx.x;
    int row0 = blockIdx.x * GBM;

    if (tid < EMB) Bs[tid] = 2.0f * b1l[tid] + b2l[tid];

    const float4* E4 = (const float4*)g_E;
    const float4* L4 = (const float4*)g_LE;
    for (int j = tid; j < GBM * EMBV; j += GT) {
        int r = j / EMBV, c = j % EMBV;
        int gr = row0 + r;
        float4 le = make_float4(0.f, 0.f, 0.f, 0.f), e = le;
        if (gr < N_NODES_) {
            le = L4[(size_t)gr * EMBV + c];
            e  = E4[(size_t)gr * EMBV + c];
        }
        float4* xr = (float4*)(Xs + r * XS);
        xr[c]        = make_float4(le.x + e.x, le.y + e.y, le.z + e.z, le.w + e.w);
        xr[EMBV + c] = make_float4(le.x * e.x, le.y * e.y, le.z * e.z, le.w * e.w);
    }
    __syncthreads();

    int tx = tid % EMBV;        // col chunk (float4), 0..19
    int ty = tid / EMBV;        // row group, 0..7 (8 rows each)

    float4 acc[8];
    #pragma unroll
    for (int r = 0; r < 8; r++) acc[r] = make_float4(0.f, 0.f, 0.f, 0.f);

    const float4* W14 = (const float4*)W1l;   // [80][20] float4
    const float4* W24 = (const float4*)W2l;
    const float*  xb  = Xs + (ty * 8) * XS;

    // k in [0,80): X = L+E against W1
    for (int k = 0; k < EMB; k += 4) {
        float4 w0 = __ldg(&W14[(k + 0) * EMBV + tx]);
        float4 w1 = __ldg(&W14[(k + 1) * EMBV + tx]);
        float4 w2 = __ldg(&W14[(k + 2) * EMBV + tx]);
        float4 w3 = __ldg(&W14[(k + 3) * EMBV + tx]);
        #pragma unroll
        for (int r = 0; r < 8; r++) {
            float4 xv = *(const float4*)(xb + r * XS + k);
            fma4(acc[r], xv.x, w0);
            fma4(acc[r], xv.y, w1);
            fma4(acc[r], xv.z, w2);
            fma4(acc[r], xv.w, w3);
        }
    }
    // k in [0,80): X = L*E (stored at col 80+k) against W2
    for (int k = 0; k < EMB; k += 4) {
        float4 w0 = __ldg(&W24[(k + 0) * EMBV + tx]);
        float4 w1 = __ldg(&W24[(k + 1) * EMBV + tx]);
        float4 w2 = __ldg(&W24[(k + 2) * EMBV + tx]);
        float4 w3 = __ldg(&W24[(k + 3) * EMBV + tx]);
        #pragma unroll
        for (int r = 0; r < 8; r++) {
            float4 xv = *(const float4*)(xb + r * XS + EMB + k);
            fma4(acc[r], xv.x, w0);
            fma4(acc[r], xv.y, w1);
            fma4(acc[r], xv.z, w2);
            fma4(acc[r], xv.w, w3);
        }
    }

    float4 b = ((const float4*)Bs)[tx];
    #pragma unroll
    for (int r = 0; r < 8; r++) {
        int gr = row0 + ty * 8 + r;
        if (gr < N_NODES_) {
            float4 v;
            v.x = acc[r].x + b.x;
            v.y = acc[r].y + b.y;
            v.z = acc[r].z + b.z;
            v.w = acc[r].w + b.w;
            v.x = (v.x > 0.f) ? v.x : 0.2f * v.x;
            v.y = (v.y > 0.f) ? v.y : 0.2f * v.y;
            v.z = (v.z > 0.f) ? v.z : 0.2f * v.z;
            v.w = (v.w > 0.f) ? v.w : 0.2f * v.w;
            ((float4*)g_E)[(size_t)gr * EMBV + tx] = v;   // in-place: safe (row-local)
        }
    }
}

// ---------------- gather + row-normalize selected rows into output ----------------
__global__ void k_gather(const int* __restrict__ u_id, const int* __restrict__ pos,
                         const int* __restrict__ neg, float* __restrict__ out, int layer) {
    int gw   = (blockIdx.x * blockDim.x + threadIdx.x) >> 5;
    int lane = threadIdx.x & 31;
    if (gw >= 3 * BATCH_) return;
    int node;
    if (gw < BATCH_)          node = u_id[gw];
    else if (gw < 2 * BATCH_) node = N_USER + pos[gw - BATCH_];
    else                      node = N_USER + neg[gw - 2 * BATCH_];

    const float4* E4 = (const float4*)g_E;
    float4 v = make_float4(0.f, 0.f, 0.f, 0.f);
    if (lane < EMBV) v = E4[(size_t)node * EMBV + lane];
    float ss = v.x * v.x + v.y * v.y + v.z * v.z + v.w * v.w;
    #pragma unroll
    for (int o = 16; o; o >>= 1) ss += __shfl_xor_sync(0xffffffffu, ss, o);
    float scale = 1.0f;
    if (layer > 0) scale = 1.0f / fmaxf(sqrtf(ss), 1e-12f);
    if (lane < EMBV) {
        float4 r = make_float4(v.x * scale, v.y * scale, v.z * scale, v.w * scale);
        ((float4*)(out + (size_t)gw * (4 * EMB) + layer * EMB))[lane] = r;
    }
}

// ---------------- launch ----------------
extern "C" void kernel_launch(void* const* d_in, const int* in_sizes, int n_in,
                              void* d_out, int out_size) {
    const int*   u_id      = (const int*)d_in[0];
    const int*   age       = (const int*)d_in[1];
    const int*   sex       = (const int*)d_in[2];
    const int*   month     = (const int*)d_in[3];
    const int*   day       = (const int*)d_in[4];
    const int*   dow       = (const int*)d_in[5];
    const int*   pos       = (const int*)d_in[6];
    const int*   neg       = (const int*)d_in[7];
    const int*   lrows     = (const int*)d_in[8];
    const int*   lcols     = (const int*)d_in[9];
    const float* lvals     = (const float*)d_in[10];
    const float* user_tab  = (const float*)d_in[11];
    const float* item_tab  = (const float*)d_in[12];
    const float* age_tab   = (const float*)d_in[13];
    const float* sex_tab   = (const float*)d_in[14];
    const float* month_tab = (const float*)d_in[15];
    const float* day_tab   = (const float*)d_in[16];
    const float* dow_tab   = (const float*)d_in[17];
    const float* W1        = (const float*)d_in[18];
    const float* b1        = (const float*)d_in[19];
    const float* W2        = (const float*)d_in[20];
    const float* b2        = (const float*)d_in[21];
    float* out = (float*)d_out;

    // CSR build (reused by all 3 layers)
    k_init<<<(N_NODES_ + 255) / 256, 256>>>();
    k_hist<<<(NNZ_ + 255) / 256, 256>>>(lrows);
    int nb = (N_NODES_ + 1023) / 1024;
    k_scan1<<<nb, 1024>>>();
    k_scan2<<<1, 1024>>>(nb);
    k_scan3<<<(N_NODES_ + 255) / 256, 256>>>();
    k_scatter<<<(NNZ_ + 255) / 256, 256>>>(lrows, lcols, lvals);

    // E0 = concat(user_tab with blended rows, item_tab)
    k_init_E<<<(N_NODES_ * EMBV + 255) / 256, 256>>>((const float4*)user_tab,
                                                     (const float4*)item_tab);
    k_winner<<<(BATCH_ + 255) / 256, 256>>>(u_id);
    k_blend<<<(BATCH_ + 255) / 256, 256>>>(u_id, age, sex, month, day, dow, user_tab,
                                           age_tab, sex_tab, month_tab, day_tab, dow_tab);

    // layer-0 slice of the output (unnormalized E0)
    k_gather<<<(3 * BATCH_ * 32 + 255) / 256, 256>>>(u_id, pos, neg, out, 0);

    for (int l = 0; l < NLAYER; l++) {
        k_spmm<<<2048, 256>>>();
        k_gemm<<<(N_NODES_ + GBM - 1) / GBM, GT>>>(W1 + (size_t)l * EMB * EMB, b1 + l * EMB,
                                                   W2 + (size_t)l * EMB * EMB, b2 + l * EMB);
        k_gather<<<(3 * BATCH_ * 32 + 255) / 256, 256>>>(u_id, pos, neg, out, l + 1);
    }
}